// round 1
// baseline (speedup 1.0000x reference)
#include <cuda_runtime.h>

#define IMG_H 256
#define IMG_W 256
#define HW    (IMG_H * IMG_W)

// accumulators: 0 ssim_sum, 1 absdiff, 2 tv_h, 3 tv_v, 4 hist_absdiff, 5 cos_sum, 6 mask_sum
__device__ double g_acc[8];

__global__ void k_zero() {
    if (threadIdx.x < 8) g_acc[threadIdx.x] = 0.0;
}

__device__ __forceinline__ float wsum(float v) {
#pragma unroll
    for (int o = 16; o; o >>= 1) v += __shfl_xor_sync(0xffffffffu, v, o);
    return v;
}

// ---------------------------------------------------------------------------
// SSIM + L1 + TV fused tiled kernel
// ---------------------------------------------------------------------------
#define TW  32
#define TH  32
#define RAD 5
#define IW  (TW + 2 * RAD)   // 42
#define IH  (TH + 2 * RAD)   // 42

__global__ __launch_bounds__(256) void k_ssim(const float* __restrict__ dz,
                                              const float* __restrict__ cw,
                                              const float* __restrict__ mk) {
    __shared__ float wg[16];
    __shared__ float sd[IH][IW + 2];
    __shared__ float sc[IH][IW + 2];
    __shared__ float hb[5][IH][TW + 1];
    __shared__ float red[8][4];

    int tid = threadIdx.x;
    if (tid == 0) {
        float tmp[11]; float s = 0.f;
#pragma unroll
        for (int i = 0; i < 11; i++) {
            float d = (float)(i - 5);
            tmp[i] = expf(-d * d / 4.5f);
            s += tmp[i];
        }
#pragma unroll
        for (int i = 0; i < 11; i++) wg[i] = tmp[i] / s;
    }

    int img = blockIdx.z;          // b*3 + c
    int b   = img / 3;
    int x0  = blockIdx.x * TW;
    int y0  = blockIdx.y * TH;
    const float* di = dz + (size_t)img * HW;
    const float* ci = cw + (size_t)img * HW;
    const float* mi = mk + (size_t)b * HW;
    __syncthreads();

    // load halo tile of dehaze = dz*mask and clean = cw*mask (zero padded)
    for (int idx = tid; idx < IH * IW; idx += 256) {
        int r = idx / IW, c = idx - r * IW;
        int gy = y0 + r - RAD, gx = x0 + c - RAD;
        float dv = 0.f, cv = 0.f;
        if ((unsigned)gy < IMG_H && (unsigned)gx < IMG_W) {
            int gi = gy * IMG_W + gx;
            float m = mi[gi];
            dv = di[gi] * m;
            cv = ci[gi] * m;
        }
        sd[r][c] = dv;
        sc[r][c] = cv;
    }
    __syncthreads();

    // horizontal gaussian pass, 5 fields
    for (int idx = tid; idx < IH * TW; idx += 256) {
        int r = idx / TW, j = idx - r * TW;
        float m1 = 0, m2 = 0, s11 = 0, s22 = 0, s12 = 0;
#pragma unroll
        for (int t = 0; t < 11; t++) {
            float w  = wg[t];
            float dv = sd[r][j + t];
            float cv = sc[r][j + t];
            m1  = fmaf(w, dv, m1);
            m2  = fmaf(w, cv, m2);
            s11 = fmaf(w * dv, dv, s11);
            s22 = fmaf(w * cv, cv, s22);
            s12 = fmaf(w * dv, cv, s12);
        }
        hb[0][r][j] = m1;  hb[1][r][j] = m2;
        hb[2][r][j] = s11; hb[3][r][j] = s22; hb[4][r][j] = s12;
    }
    __syncthreads();

    const float C1c = 1e-4f, C2c = 9e-4f;
    float a_ssim = 0.f, a_abs = 0.f, a_tvh = 0.f, a_tvv = 0.f;

    // vertical pass + ssim map + L1 + TV
    for (int idx = tid; idx < TH * TW; idx += 256) {
        int i = idx / TW, j = idx - i * TW;
        float mu1 = 0, mu2 = 0, e11 = 0, e22 = 0, e12 = 0;
#pragma unroll
        for (int t = 0; t < 11; t++) {
            float w = wg[t];
            mu1 = fmaf(w, hb[0][i + t][j], mu1);
            mu2 = fmaf(w, hb[1][i + t][j], mu2);
            e11 = fmaf(w, hb[2][i + t][j], e11);
            e22 = fmaf(w, hb[3][i + t][j], e22);
            e12 = fmaf(w, hb[4][i + t][j], e12);
        }
        float m1s = mu1 * mu1, m2s = mu2 * mu2, m12 = mu1 * mu2;
        float num = (2.f * m12 + C1c) * (2.f * (e12 - m12) + C2c);
        float den = (m1s + m2s + C1c) * ((e11 - m1s) + (e22 - m2s) + C2c);
        a_ssim += num / den;

        float dv = sd[i + RAD][j + RAD];
        float cv = sc[i + RAD][j + RAD];
        a_abs += fabsf(dv - cv);
        if (x0 + j + 1 < IMG_W) a_tvh += fabsf(dv - sd[i + RAD][j + RAD + 1]);
        if (y0 + i + 1 < IMG_H) a_tvv += fabsf(dv - sd[i + RAD + 1][j + RAD]);
    }

    // block reduce 4 scalars
    int lane = tid & 31, wid = tid >> 5;
    a_ssim = wsum(a_ssim); a_abs = wsum(a_abs);
    a_tvh  = wsum(a_tvh);  a_tvv = wsum(a_tvv);
    if (lane == 0) {
        red[wid][0] = a_ssim; red[wid][1] = a_abs;
        red[wid][2] = a_tvh;  red[wid][3] = a_tvv;
    }
    __syncthreads();
    if (tid < 4) {
        float s = 0.f;
#pragma unroll
        for (int w = 0; w < 8; w++) s += red[w][tid];
        atomicAdd(&g_acc[tid], (double)s);
    }
}

// ---------------------------------------------------------------------------
// per-(b,c) 64-bin histogram + |normal_hist - GT_hist| accumulation
// ---------------------------------------------------------------------------
__global__ __launch_bounds__(256) void k_hist(const float* __restrict__ gt,
                                              const float* __restrict__ nh) {
    __shared__ int sh[8][64];
    int tid = threadIdx.x, wid = tid >> 5, lane = tid & 31;
    for (int i = tid; i < 8 * 64; i += 256) ((int*)sh)[i] = 0;
    __syncthreads();

    int img = blockIdx.x;
    const float* g = gt + (size_t)img * HW;
    for (int i = tid; i < HW; i += 256) {
        float x = g[i];
        float v = x * 2.f - 1.f;                       // match reference rounding
        int idx = (int)floorf((v + 1.f) * 0.5f * 64.f);
        idx = min(63, max(0, idx));
        atomicAdd(&sh[wid][idx], 1);
    }
    __syncthreads();

    float a = 0.f;
    if (tid < 64) {
        int tot = 0;
#pragma unroll
        for (int w = 0; w < 8; w++) tot += sh[w][tid];
        float hval = (float)tot / (float)HW;
        a = fabsf(nh[(size_t)img * 64 + tid] - hval);
    }
    a = wsum(a);
    if (lane == 0 && wid < 2) atomicAdd(&g_acc[4], (double)a);
}

// ---------------------------------------------------------------------------
// cosine / normal loss + mask sum (streaming)
// ---------------------------------------------------------------------------
__global__ __launch_bounds__(256) void k_cos(const float* __restrict__ pr,
                                             const float* __restrict__ gt,
                                             const float* __restrict__ mk,
                                             int npix) {
    __shared__ float red[8][2];
    int stride = gridDim.x * blockDim.x;
    float a_cos = 0.f, a_m = 0.f;

    for (int p = blockIdx.x * blockDim.x + threadIdx.x; p < npix; p += stride) {
        int b   = p >> 16;
        int rem = p & 65535;
        size_t base = (size_t)b * 3 * HW + rem;
        float m  = mk[(size_t)b * HW + rem];
        float p0 = pr[base] * m, p1 = pr[base + HW] * m, p2 = pr[base + 2 * HW] * m;
        float g0 = gt[base] * m, g1 = gt[base + HW] * m, g2 = gt[base + 2 * HW] * m;

        float npn = sqrtf(p0 * p0 + p1 * p1 + p2 * p2);
        float dn  = fmaxf(npn, 1e-12f);
        p0 /= dn; p1 /= dn; p2 /= dn;

        float n0 = (g0 * 2.f - 1.f) * m;
        float n1 = (g1 * 2.f - 1.f) * m;
        float n2 = (g2 * 2.f - 1.f) * m;

        float dot = p0 * n0 + p1 * n1 + p2 * n2;
        float na  = fmaxf(sqrtf(p0 * p0 + p1 * p1 + p2 * p2), 1e-8f);
        float nb  = fmaxf(sqrtf(n0 * n0 + n1 * n1 + n2 * n2), 1e-8f);
        a_cos += 1.f - dot / (na * nb);
        a_m   += m;
    }

    int lane = threadIdx.x & 31, wid = threadIdx.x >> 5;
    a_cos = wsum(a_cos); a_m = wsum(a_m);
    if (lane == 0) { red[wid][0] = a_cos; red[wid][1] = a_m; }
    __syncthreads();
    if (threadIdx.x < 2) {
        float s = 0.f;
#pragma unroll
        for (int w = 0; w < 8; w++) s += red[w][threadIdx.x];
        atomicAdd(&g_acc[5 + threadIdx.x], (double)s);
    }
}

// ---------------------------------------------------------------------------
// final combine
// ---------------------------------------------------------------------------
__global__ void k_final(float* __restrict__ out, int B) {
    double N        = (double)B * 3.0 * (double)HW;
    double L_dehaze = g_acc[1] / N;
    double L_ssim   = 1.0 - g_acc[0] / N;
    double cnt_tv   = (double)B * 3.0 * 256.0 * 255.0;
    double L_tv     = g_acc[2] / cnt_tv + g_acc[3] / cnt_tv;
    double L_hist   = g_acc[4] / ((double)B * 3.0 * 64.0);
    double M        = g_acc[6];
    double bg       = (double)B * (double)HW - M;
    double L_normal = (g_acc[5] - bg) / M;
    double total = 10.0 * L_dehaze + L_ssim + L_tv + L_hist + 100.0 * L_normal;
    out[0] = (float)total;
}

// ---------------------------------------------------------------------------
extern "C" void kernel_launch(void* const* d_in, const int* in_sizes, int n_in,
                              void* d_out, int out_size) {
    const float* predict = (const float*)d_in[0];
    const float* gtruth  = (const float*)d_in[1];
    const float* dz      = (const float*)d_in[2];
    const float* cw      = (const float*)d_in[3];
    const float* nh      = (const float*)d_in[4];
    const float* mk      = (const float*)d_in[5];
    int B = in_sizes[0] / (3 * IMG_H * IMG_W);

    k_zero<<<1, 32>>>();

    dim3 gssim(IMG_W / TW, IMG_H / TH, B * 3);
    k_ssim<<<gssim, 256>>>(dz, cw, mk);

    k_hist<<<B * 3, 256>>>(gtruth, nh);

    int npix = B * HW;
    k_cos<<<1184, 256>>>(predict, gtruth, mk, npix);

    k_final<<<1, 1>>>((float*)d_out, B);
}

// round 2
// speedup vs baseline: 1.3084x; 1.3084x over previous
#include <cuda_runtime.h>

#define IMG_H 256
#define IMG_W 256
#define HW    (IMG_H * IMG_W)

// accumulators: 0 ssim_sum, 1 absdiff, 2 tv_h, 3 tv_v, 4 hist_absdiff, 5 cos_sum, 6 mask_sum
__device__ double g_acc[8];

__constant__ float c_wg[11] = {
    0.0010283748f, 0.0075987582f, 0.0360007696f, 0.1093606895f, 0.2130055325f,
    0.2660117251f, 0.2130055325f, 0.1093606895f, 0.0360007696f, 0.0075987582f,
    0.0010283748f};

__global__ void k_zero() {
    if (threadIdx.x < 8) g_acc[threadIdx.x] = 0.0;
}

__device__ __forceinline__ float wsum(float v) {
#pragma unroll
    for (int o = 16; o; o >>= 1) v += __shfl_xor_sync(0xffffffffu, v, o);
    return v;
}

// ---- f32x2 packed helpers (FFMA2 etc., only reachable via PTX) -------------
__device__ __forceinline__ double pk(float lo, float hi) {
    double r; asm("mov.b64 %0, {%1, %2};" : "=d"(r) : "f"(lo), "f"(hi)); return r;
}
__device__ __forceinline__ void upk(double v, float& lo, float& hi) {
    asm("mov.b64 {%0, %1}, %2;" : "=f"(lo), "=f"(hi) : "d"(v));
}
__device__ __forceinline__ double fma2(double a, double b, double c) {
    double r; asm("fma.rn.f32x2 %0, %1, %2, %3;" : "=d"(r) : "d"(a), "d"(b), "d"(c)); return r;
}
__device__ __forceinline__ double mul2(double a, double b) {
    double r; asm("mul.rn.f32x2 %0, %1, %2;" : "=d"(r) : "d"(a), "d"(b)); return r;
}
__device__ __forceinline__ double add2(double a, double b) {
    double r; asm("add.rn.f32x2 %0, %1, %2;" : "=d"(r) : "d"(a), "d"(b)); return r;
}

// ---------------------------------------------------------------------------
// SSIM + L1 + TV fused tiled kernel (separable 11-tap gaussian, f32x2 math)
// ---------------------------------------------------------------------------
#define TW  32
#define TH  32
#define RAD 5
#define IW  42
#define IH  42
#define SDW 44   // sd/sc row stride (16B aligned rows)
#define HBW 36   // hb row stride (16B aligned rows, even for LDS.64)

__global__ __launch_bounds__(256) void k_ssim(const float* __restrict__ dz,
                                              const float* __restrict__ cw,
                                              const float* __restrict__ mk) {
    __shared__ float sd[IH][SDW];
    __shared__ float sc[IH][SDW];
    __shared__ float hb[5][IH][HBW];
    __shared__ float red[8][4];

    int tid = threadIdx.x;
    int img = blockIdx.z;          // b*3 + c
    int b   = img / 3;
    int x0  = blockIdx.x * TW;
    int y0  = blockIdx.y * TH;
    const float* di = dz + (size_t)img * HW;
    const float* ci = cw + (size_t)img * HW;
    const float* mi = mk + (size_t)b * HW;

    // load halo tile of dehaze = dz*mask and clean = cw*mask (zero padded)
    for (int idx = tid; idx < IH * IW; idx += 256) {
        int r = idx / IW, c = idx - r * IW;
        int gy = y0 + r - RAD, gx = x0 + c - RAD;
        float dv = 0.f, cv = 0.f;
        if ((unsigned)gy < IMG_H && (unsigned)gx < IMG_W) {
            int gi = gy * IMG_W + gx;
            float m = mi[gi];
            dv = di[gi] * m;
            cv = ci[gi] * m;
        }
        sd[r][c] = dv;
        sc[r][c] = cv;
    }

    // packed symmetric weights (w[t] == w[10-t])
    double w2[6];
#pragma unroll
    for (int t = 0; t < 6; t++) w2[t] = pk(c_wg[t], c_wg[t]);
    __syncthreads();

    // ---- horizontal pass: 4 outputs / work item, packed pairs ----
    for (int wi = tid; wi < IH * 8; wi += 256) {
        int r = wi >> 3, jb = (wi & 7) << 2;
        float dv[16], cv[16];
        const float4* pd4 = (const float4*)&sd[r][jb];
        const float4* pc4 = (const float4*)&sc[r][jb];
#pragma unroll
        for (int q = 0; q < 4; q++) {
            ((float4*)dv)[q] = pd4[q];
            ((float4*)cv)[q] = pc4[q];
        }
        double Am1 = 0, Am2 = 0, As11 = 0, As22 = 0, As12 = 0;
        double Bm1 = 0, Bm2 = 0, Bs11 = 0, Bs22 = 0, Bs12 = 0;
#pragma unroll
        for (int t = 0; t < 11; t++) {
            double w   = w2[t < 6 ? t : 10 - t];
            double pd0 = pk(dv[t], dv[t + 1]),     pc0 = pk(cv[t], cv[t + 1]);
            double pd1 = pk(dv[t + 2], dv[t + 3]), pc1 = pk(cv[t + 2], cv[t + 3]);
            double td0 = mul2(w, pd0), tc0 = mul2(w, pc0);
            double td1 = mul2(w, pd1), tc1 = mul2(w, pc1);
            Am1 = add2(Am1, td0); Am2 = add2(Am2, tc0);
            As11 = fma2(td0, pd0, As11); As22 = fma2(tc0, pc0, As22); As12 = fma2(td0, pc0, As12);
            Bm1 = add2(Bm1, td1); Bm2 = add2(Bm2, tc1);
            Bs11 = fma2(td1, pd1, Bs11); Bs22 = fma2(tc1, pc1, Bs22); Bs12 = fma2(td1, pc1, Bs12);
        }
        float4 o;
        upk(Am1,  o.x, o.y); upk(Bm1,  o.z, o.w); *(float4*)&hb[0][r][jb] = o;
        upk(Am2,  o.x, o.y); upk(Bm2,  o.z, o.w); *(float4*)&hb[1][r][jb] = o;
        upk(As11, o.x, o.y); upk(Bs11, o.z, o.w); *(float4*)&hb[2][r][jb] = o;
        upk(As22, o.x, o.y); upk(Bs22, o.z, o.w); *(float4*)&hb[3][r][jb] = o;
        upk(As12, o.x, o.y); upk(Bs12, o.z, o.w); *(float4*)&hb[4][r][jb] = o;
    }
    __syncthreads();

    // ---- vertical pass: each thread owns a column pair x 2 output rows ----
    int jp = tid & 15, ig = tid >> 4;
    int j = jp * 2, i0 = ig * 2;

    double a0[5] = {0, 0, 0, 0, 0};
    double a1[5] = {0, 0, 0, 0, 0};
#pragma unroll
    for (int t = 0; t < 12; t++) {
        double v[5];
#pragma unroll
        for (int f = 0; f < 5; f++) v[f] = *(const double*)&hb[f][i0 + t][j];
        if (t < 11) {
            double w = w2[t < 6 ? t : 10 - t];
#pragma unroll
            for (int f = 0; f < 5; f++) a0[f] = fma2(w, v[f], a0[f]);
        }
        if (t >= 1) {
            double w = w2[(t - 1) < 6 ? (t - 1) : 11 - t];
#pragma unroll
            for (int f = 0; f < 5; f++) a1[f] = fma2(w, v[f], a1[f]);
        }
    }

    const float C1c = 1e-4f, C2c = 9e-4f;
    float a_ssim = 0.f, a_abs = 0.f, a_tvh = 0.f, a_tvv = 0.f;

#pragma unroll
    for (int ir = 0; ir < 2; ir++) {
        double* A = ir ? a1 : a0;
        float mu1[2], mu2[2], e11[2], e22[2], e12[2];
        upk(A[0], mu1[0], mu1[1]);
        upk(A[1], mu2[0], mu2[1]);
        upk(A[2], e11[0], e11[1]);
        upk(A[3], e22[0], e22[1]);
        upk(A[4], e12[0], e12[1]);
#pragma unroll
        for (int ic = 0; ic < 2; ic++) {
            int i = i0 + ir, jj = j + ic;
            float m1 = mu1[ic], m2 = mu2[ic];
            float m1s = m1 * m1, m2s = m2 * m2, m12 = m1 * m2;
            float num = (2.f * m12 + C1c) * (2.f * (e12[ic] - m12) + C2c);
            float den = (m1s + m2s + C1c) * ((e11[ic] - m1s) + (e22[ic] - m2s) + C2c);
            a_ssim += num / den;

            float dv = sd[i + RAD][jj + RAD];
            float cvv = sc[i + RAD][jj + RAD];
            a_abs += fabsf(dv - cvv);
            if (x0 + jj + 1 < IMG_W) a_tvh += fabsf(dv - sd[i + RAD][jj + RAD + 1]);
            if (y0 + i + 1 < IMG_H)  a_tvv += fabsf(dv - sd[i + RAD + 1][jj + RAD]);
        }
    }

    // block reduce 4 scalars
    int lane = tid & 31, wid = tid >> 5;
    a_ssim = wsum(a_ssim); a_abs = wsum(a_abs);
    a_tvh  = wsum(a_tvh);  a_tvv = wsum(a_tvv);
    if (lane == 0) {
        red[wid][0] = a_ssim; red[wid][1] = a_abs;
        red[wid][2] = a_tvh;  red[wid][3] = a_tvv;
    }
    __syncthreads();
    if (tid < 4) {
        float s = 0.f;
#pragma unroll
        for (int w = 0; w < 8; w++) s += red[w][tid];
        atomicAdd(&g_acc[tid], (double)s);
    }
}

// ---------------------------------------------------------------------------
// per-(b,c) 64-bin histogram + |normal_hist - GT_hist| accumulation
// ---------------------------------------------------------------------------
__global__ __launch_bounds__(256) void k_hist(const float4* __restrict__ gt,
                                              const float* __restrict__ nh) {
    __shared__ int sh[8][64];
    int tid = threadIdx.x, wid = tid >> 5, lane = tid & 31;
    for (int i = tid; i < 8 * 64; i += 256) ((int*)sh)[i] = 0;
    __syncthreads();

    int img = blockIdx.x;
    const float4* g = gt + (size_t)img * (HW / 4);
    for (int i = tid; i < HW / 4; i += 256) {
        float4 x = g[i];
        float xs[4] = {x.x, x.y, x.z, x.w};
#pragma unroll
        for (int k = 0; k < 4; k++) {
            float v = xs[k] * 2.f - 1.f;
            int idx = (int)floorf((v + 1.f) * 0.5f * 64.f);
            idx = min(63, max(0, idx));
            atomicAdd(&sh[wid][idx], 1);
        }
    }
    __syncthreads();

    float a = 0.f;
    if (tid < 64) {
        int tot = 0;
#pragma unroll
        for (int w = 0; w < 8; w++) tot += sh[w][tid];
        float hval = (float)tot / (float)HW;
        a = fabsf(nh[(size_t)img * 64 + tid] - hval);
    }
    a = wsum(a);
    if (lane == 0 && wid < 2) atomicAdd(&g_acc[4], (double)a);
}

// ---------------------------------------------------------------------------
// cosine / normal loss + mask sum (float4 streaming)
// ---------------------------------------------------------------------------
__device__ __forceinline__ void cospix(float m, float a0, float a1, float a2,
                                       float g0, float g1, float g2,
                                       float& ac, float& am) {
    float q0 = a0 * m, q1 = a1 * m, q2 = a2 * m;
    float L = sqrtf(q0 * q0 + q1 * q1 + q2 * q2);
    float n0 = fmaf(g0 * m, 2.f, -1.f) * m;
    float n1 = fmaf(g1 * m, 2.f, -1.f) * m;
    float n2 = fmaf(g2 * m, 2.f, -1.f) * m;
    float dot = q0 * n0 + q1 * n1 + q2 * n2;
    float nb = sqrtf(n0 * n0 + n1 * n1 + n2 * n2);
    float den = fmaxf(L, 1e-12f) * fmaxf(nb, 1e-8f);
    ac += 1.f - dot / den;
    am += m;
}

#define HW4 (HW / 4)

__global__ __launch_bounds__(256) void k_cos(const float4* __restrict__ pr,
                                             const float4* __restrict__ gt,
                                             const float4* __restrict__ mk,
                                             int nitems) {
    __shared__ float red[8][2];
    int stride = gridDim.x * blockDim.x;
    float a_cos = 0.f, a_m = 0.f;

    for (int p = blockIdx.x * blockDim.x + threadIdx.x; p < nitems; p += stride) {
        int b   = p >> 14;       // HW4 = 16384 items per image
        int rem = p & 16383;
        size_t base = (size_t)b * 3 * HW4 + rem;
        float4 m4 = mk[(size_t)b * HW4 + rem];
        float4 p0 = pr[base], p1 = pr[base + HW4], p2 = pr[base + 2 * HW4];
        float4 g0 = gt[base], g1 = gt[base + HW4], g2 = gt[base + 2 * HW4];
        cospix(m4.x, p0.x, p1.x, p2.x, g0.x, g1.x, g2.x, a_cos, a_m);
        cospix(m4.y, p0.y, p1.y, p2.y, g0.y, g1.y, g2.y, a_cos, a_m);
        cospix(m4.z, p0.z, p1.z, p2.z, g0.z, g1.z, g2.z, a_cos, a_m);
        cospix(m4.w, p0.w, p1.w, p2.w, g0.w, g1.w, g2.w, a_cos, a_m);
    }

    int lane = threadIdx.x & 31, wid = threadIdx.x >> 5;
    a_cos = wsum(a_cos); a_m = wsum(a_m);
    if (lane == 0) { red[wid][0] = a_cos; red[wid][1] = a_m; }
    __syncthreads();
    if (threadIdx.x < 2) {
        float s = 0.f;
#pragma unroll
        for (int w = 0; w < 8; w++) s += red[w][threadIdx.x];
        atomicAdd(&g_acc[5 + threadIdx.x], (double)s);
    }
}

// ---------------------------------------------------------------------------
// final combine
// ---------------------------------------------------------------------------
__global__ void k_final(float* __restrict__ out, int B) {
    double N        = (double)B * 3.0 * (double)HW;
    double L_dehaze = g_acc[1] / N;
    double L_ssim   = 1.0 - g_acc[0] / N;
    double cnt_tv   = (double)B * 3.0 * 256.0 * 255.0;
    double L_tv     = g_acc[2] / cnt_tv + g_acc[3] / cnt_tv;
    double L_hist   = g_acc[4] / ((double)B * 3.0 * 64.0);
    double M        = g_acc[6];
    double bg       = (double)B * (double)HW - M;
    double L_normal = (g_acc[5] - bg) / M;
    double total = 10.0 * L_dehaze + L_ssim + L_tv + L_hist + 100.0 * L_normal;
    out[0] = (float)total;
}

// ---------------------------------------------------------------------------
extern "C" void kernel_launch(void* const* d_in, const int* in_sizes, int n_in,
                              void* d_out, int out_size) {
    const float* predict = (const float*)d_in[0];
    const float* gtruth  = (const float*)d_in[1];
    const float* dz      = (const float*)d_in[2];
    const float* cw      = (const float*)d_in[3];
    const float* nh      = (const float*)d_in[4];
    const float* mk      = (const float*)d_in[5];
    int B = in_sizes[0] / (3 * IMG_H * IMG_W);

    k_zero<<<1, 32>>>();

    dim3 gssim(IMG_W / TW, IMG_H / TH, B * 3);
    k_ssim<<<gssim, 256>>>(dz, cw, mk);

    k_hist<<<B * 3, 256>>>((const float4*)gtruth, nh);

    int nitems = B * HW4;
    k_cos<<<1184, 256>>>((const float4*)predict, (const float4*)gtruth,
                         (const float4*)mk, nitems);

    k_final<<<1, 1>>>((float*)d_out, B);
}